// round 3
// baseline (speedup 1.0000x reference)
#include <cuda_runtime.h>
#include <math.h>

#define BSZ  128
#define NDIM 256
#define HDIM 1024

#define ALPHA 60.0f
#define BETA  20.0f
#define EPSC  1e-8f

#define GRID 128

// ---- scratch (allocation-free: __device__ globals) ----
__device__ float g_H [3][BSZ * HDIM];     // tanh hidden f,g,k
__device__ float g_D [BSZ * HDIM];        // 1 - Hk^2
__device__ float g_p2[3][4][BSZ * NDIM];  // stage2 split-K(4) partials (f,g,k pre-bias)
__device__ float g_p3[2][2][BSZ * HDIM];  // stage3 split-K(2) partials (pre *D)
__device__ float g_p4[2][8][BSZ * NDIM];  // stage4 split-K(8) partials (Jf, JG)

// ---- software grid barrier state ----
__device__ unsigned g_bar   = 0;
__device__ unsigned g_epoch = 0;

__device__ __forceinline__ void grid_barrier(unsigned target_epoch)
{
    __threadfence();            // make this thread's writes visible chip-wide
    __syncthreads();
    if (threadIdx.x == 0) {
        unsigned prev = atomicAdd(&g_bar, 1);
        if (prev == GRID - 1) {
            g_bar = 0;
            __threadfence();    // reset visible before epoch bump
            atomicAdd(&g_epoch, 1);
        } else {
            while ((int)(*(volatile unsigned*)&g_epoch - target_epoch) < 0)
                __nanosleep(64);
        }
    }
    __syncthreads();
    __threadfence();            // acquire side
}

__device__ __forceinline__ float4 ld4(const float* p)
{
    return *reinterpret_cast<const float4*>(p);
}

// ---- A-tile loaders (k is GLOBAL k index; always float4-aligned) ----
struct DirectA {                 // plain row-major matrix
    const float* p; int ld;
    __device__ __forceinline__ float4 operator()(int row, int k) const {
        return ld4(&p[(size_t)row * ld + k]);
    }
};
struct SumP2A {                  // f or g = bias + sum of 4 stage2 partials
    const float* q0; const float* q1; const float* q2; const float* q3;
    const float* bias;
    __device__ __forceinline__ float4 operator()(int row, int k) const {
        const size_t o = (size_t)row * NDIM + k;
        float4 v = ld4(bias + k);
        float4 a = ld4(q0 + o), b = ld4(q1 + o), c = ld4(q2 + o), d = ld4(q3 + o);
        v.x += a.x + b.x + c.x + d.x;
        v.y += a.y + b.y + c.y + d.y;
        v.z += a.z + b.z + c.z + d.z;
        v.w += a.w + b.w + c.w + d.w;
        return v;
    }
};
struct DvA {                     // dv = (p3_0 + p3_1) * D
    const float* q0; const float* q1; const float* D;
    __device__ __forceinline__ float4 operator()(int row, int k) const {
        const size_t o = (size_t)row * HDIM + k;
        float4 a = ld4(q0 + o), b = ld4(q1 + o), d = ld4(D + o);
        float4 v;
        v.x = (a.x + b.x) * d.x; v.y = (a.y + b.y) * d.y;
        v.z = (a.z + b.z) * d.z; v.w = (a.w + b.w) * d.w;
        return v;
    }
};

// ============================================================
// 64x64 tile GEMM, BK=16, 256 threads, 4x4 per thread.
// BT=true : C[m,n] = sum_k A[m,k] * B[n*ldb+k]   (NT)
// BT=false: C[m,n] = sum_k A[m,k] * B[k*ldb+n]   (NN)
// B pointer pre-offset to the K-chunk; A loader gets global k via kbase.
// ============================================================
template <bool BT, class AL>
__device__ __forceinline__ void gemm_tile(
    const AL& la, int kbase,
    const float* __restrict__ B, int ldb,
    int K, int bm, int bn, float acc[4][4],
    float (&As)[16][64], float (&Bs)[16][64])
{
    const int tid = threadIdx.x;
    const int tm = (tid >> 4) * 4;
    const int tn = (tid & 15) * 4;
    const int lr = tid >> 2;          // 0..63
    const int lc = (tid & 3) * 4;     // 0,4,8,12
    const int br = tid >> 4;          // 0..15
    const int bc = (tid & 15) * 4;    // 0..60

    for (int k0 = 0; k0 < K; k0 += 16) {
        float4 av = la(bm + lr, kbase + k0 + lc);
        As[lc + 0][lr] = av.x;
        As[lc + 1][lr] = av.y;
        As[lc + 2][lr] = av.z;
        As[lc + 3][lr] = av.w;
        if (BT) {
            float4 bv = ld4(&B[(size_t)(bn + lr) * ldb + k0 + lc]);
            Bs[lc + 0][lr] = bv.x;
            Bs[lc + 1][lr] = bv.y;
            Bs[lc + 2][lr] = bv.z;
            Bs[lc + 3][lr] = bv.w;
        } else {
            float4 bv = ld4(&B[(size_t)(k0 + br) * ldb + bn + bc]);
            *reinterpret_cast<float4*>(&Bs[br][bc]) = bv;
        }
        __syncthreads();
#pragma unroll
        for (int kk = 0; kk < 16; kk++) {
            float4 a4 = ld4(&As[kk][tm]);
            float4 b4 = ld4(&Bs[kk][tn]);
            float aa[4] = {a4.x, a4.y, a4.z, a4.w};
            float bb[4] = {b4.x, b4.y, b4.z, b4.w};
#pragma unroll
            for (int i = 0; i < 4; i++)
#pragma unroll
                for (int j = 0; j < 4; j++)
                    acc[i][j] = fmaf(aa[i], bb[j], acc[i][j]);
        }
        __syncthreads();
    }
}

__device__ __forceinline__ void store_acc(float* __restrict__ out, int ld,
                                          int bm, int bn, float acc[4][4])
{
    const int tid = threadIdx.x;
    const int tm = (tid >> 4) * 4, tn = (tid & 15) * 4;
#pragma unroll
    for (int i = 0; i < 4; i++) {
        float4 v = make_float4(acc[i][0], acc[i][1], acc[i][2], acc[i][3]);
        *reinterpret_cast<float4*>(&out[(size_t)(bm + tm + i) * ld + bn + tn]) = v;
    }
}

// ============================================================
// One persistent kernel, 5 phases, 4 grid barriers.
// ============================================================
__global__ __launch_bounds__(256) void fused_kernel(
    const float* __restrict__ x,
    const float* __restrict__ Wf1, const float* __restrict__ bf1,
    const float* __restrict__ Wf2, const float* __restrict__ bf2,
    const float* __restrict__ Wg1, const float* __restrict__ bg1,
    const float* __restrict__ Wg2, const float* __restrict__ bg2,
    const float* __restrict__ Wk1, const float* __restrict__ bk1,
    const float* __restrict__ Wk2, const float* __restrict__ bk2,
    float* __restrict__ out)
{
    __shared__ float As[16][64];
    __shared__ float Bs[16][64];
    __shared__ unsigned s_e0;

    const int tid = threadIdx.x;
    const int bid = blockIdx.x;
    if (tid == 0) s_e0 = *(volatile unsigned*)&g_epoch;
    __syncthreads();
    const unsigned e0 = s_e0;

    // ---------- Phase 1: H[z] = tanh(x @ W1[z]^T + b1[z]);  D = 1-Hk^2 ----------
    // 96 tiles: z in [0,3), 2 m-tiles x 16 n-tiles. K=256, no split.
    if (bid < 96) {
        const int z = bid / 32, r = bid % 32;
        const int bm = (r / 16) * 64, bn = (r % 16) * 64;
        const float* W    = (z == 0) ? Wf1 : (z == 1) ? Wg1 : Wk1;
        const float* bias = (z == 0) ? bf1 : (z == 1) ? bg1 : bk1;
        float acc[4][4] = {};
        DirectA la{x, NDIM};
        gemm_tile<true>(la, 0, W, NDIM, NDIM, bm, bn, acc, As, Bs);

        const int tm = (tid >> 4) * 4, tn = (tid & 15) * 4;
        float* H = g_H[z];
#pragma unroll
        for (int i = 0; i < 4; i++) {
            const int row = bm + tm + i;
#pragma unroll
            for (int j = 0; j < 4; j++) {
                const int col = bn + tn + j;
                const float t = tanhf(acc[i][j] + bias[col]);
                H[row * HDIM + col] = t;
                if (z == 2) g_D[row * HDIM + col] = 1.0f - t * t;
            }
        }
    }
    grid_barrier(e0 + 1);

    // ---------- Phase 2: p2[z][s] = H[z][:,chunk] @ W2[z][:,chunk]^T ----------
    // 96 tiles: z, s in [0,4) (K chunk 256), 2 m x 4 n.
    if (bid < 96) {
        const int z = bid / 32, r = bid % 32;
        const int s = r / 8, rr = r % 8;
        const int bm = (rr / 4) * 64, bn = (rr % 4) * 64;
        const float* W = (z == 0) ? Wf2 : (z == 1) ? Wg2 : Wk2;
        float acc[4][4] = {};
        DirectA la{g_H[z], HDIM};
        gemm_tile<true>(la, s * 256, W + s * 256, HDIM, 256, bm, bn, acc, As, Bs);
        store_acc(g_p2[z][s], NDIM, bm, bn, acc);
    }
    grid_barrier(e0 + 2);

    // ---------- Phase 3: p3[z][s] = {f,g}[:,chunk] @ Wk2[chunk,:]  (NN) ----------
    // f,g reconstructed on the fly from p2 + bias. 128 tiles: z, s in [0,2) (chunk 128),
    // 2 m x 16 n.
    {
        const int z = bid / 64, r = bid % 64;
        const int s = r / 32, rr = r % 32;
        const int bm = (rr / 16) * 64, bn = (rr % 16) * 64;
        float acc[4][4] = {};
        SumP2A la{g_p2[z][0], g_p2[z][1], g_p2[z][2], g_p2[z][3],
                  (z == 0) ? bf2 : bg2};
        gemm_tile<false>(la, s * 128, Wk2 + (size_t)(s * 128) * HDIM, HDIM,
                         128, bm, bn, acc, As, Bs);
        store_acc(g_p3[z][s], HDIM, bm, bn, acc);
    }
    grid_barrier(e0 + 3);

    // ---------- Phase 4: p4[z][s] = dv[z][:,chunk] @ Wk1[chunk,:]  (NN) ----------
    // dv reconstructed on the fly: (p3_0+p3_1)*D. 128 tiles: z, s in [0,8) (chunk 128),
    // 2 m x 4 n.
    {
        const int z = bid / 64, r = bid % 64;
        const int s = r / 8, rr = r % 8;
        const int bm = (rr / 4) * 64, bn = (rr % 4) * 64;
        float acc[4][4] = {};
        DvA la{g_p3[z][0], g_p3[z][1], g_D};
        gemm_tile<false>(la, s * 128, Wk1 + (size_t)(s * 128) * NDIM, NDIM,
                         128, bm, bn, acc, As, Bs);
        store_acc(g_p4[z][s], NDIM, bm, bn, acc);
    }
    grid_barrier(e0 + 4);

    // ---------- Phase 5: reduce + norms + mask + output; block b -> row b ----------
    if (bid < BSZ) {
        const int b = bid, i = tid;               // i in [0,256)
        const int idx = b * NDIM + i;

        float jfv = 0.f, jgv = 0.f;
#pragma unroll
        for (int s = 0; s < 8; s++) {
            jfv += g_p4[0][s][idx];
            jgv += g_p4[1][s][idx];
        }
        float fv = bf2[i], gv = bg2[i], kv = bk2[i];
#pragma unroll
        for (int s = 0; s < 4; s++) {
            fv += g_p2[0][s][idx];
            gv += g_p2[1][s][idx];
            kv += g_p2[2][s][idx];
        }

        float kn2 = kv * kv;
        float jf2 = jfv * jfv;
        float dt  = kv * jgv;
#pragma unroll
        for (int off = 16; off > 0; off >>= 1) {
            kn2 += __shfl_down_sync(0xffffffffu, kn2, off);
            jf2 += __shfl_down_sync(0xffffffffu, jf2, off);
            dt  += __shfl_down_sync(0xffffffffu, dt,  off);
        }

        __shared__ float s_kn2[8], s_jf2[8], s_dt[8];
        __shared__ float s_scale;
        const int warp = i >> 5, lane = i & 31;
        if (lane == 0) { s_kn2[warp] = kn2; s_jf2[warp] = jf2; s_dt[warp] = dt; }
        __syncthreads();
        if (i == 0) {
            float tkn2 = 0.f, tjf2 = 0.f, tdt = 0.f;
#pragma unroll
            for (int w = 0; w < 8; w++) { tkn2 += s_kn2[w]; tjf2 += s_jf2[w]; tdt += s_dt[w]; }
            const float kn   = sqrtf(tkn2);
            const float kn9  = tkn2 * tkn2 * tkn2 * tkn2 * kn;
            const float kn10 = kn9 * kn;
            const float c1 = sqrtf(tjf2) - ALPHA * kn9;
            const float c2 = tdt - BETA * kn10;
            const bool mask = (c1 > EPSC) || (c2 < -EPSC);
            s_scale = mask ? 0.5f : 1.0f;
        }
        __syncthreads();
        out[idx] = s_scale * (fv + gv);
    }
}

// inputs: 0:t 1:x 2:Wf1 3:bf1 4:Wf2 5:bf2 6:Wg1 7:bg1 8:Wg2 9:bg2 10:Wk1 11:bk1 12:Wk2 13:bk2
extern "C" void kernel_launch(void* const* d_in, const int* in_sizes, int n_in,
                              void* d_out, int out_size)
{
    const float* x   = (const float*)d_in[1];
    const float* Wf1 = (const float*)d_in[2];
    const float* bf1 = (const float*)d_in[3];
    const float* Wf2 = (const float*)d_in[4];
    const float* bf2 = (const float*)d_in[5];
    const float* Wg1 = (const float*)d_in[6];
    const float* bg1 = (const float*)d_in[7];
    const float* Wg2 = (const float*)d_in[8];
    const float* bg2 = (const float*)d_in[9];
    const float* Wk1 = (const float*)d_in[10];
    const float* bk1 = (const float*)d_in[11];
    const float* Wk2 = (const float*)d_in[12];
    const float* bk2 = (const float*)d_in[13];
    float* out = (float*)d_out;

    fused_kernel<<<GRID, 256>>>(x, Wf1, bf1, Wf2, bf2, Wg1, bg1, Wg2, bg2,
                                Wk1, bk1, Wk2, bk2, out);
}

// round 4
// speedup vs baseline: 1.0685x; 1.0685x over previous
#include <cuda_runtime.h>
#include <math.h>

typedef unsigned long long ull;

#define BSZ  128
#define NDIM 256
#define HDIM 1024

#define ALPHA 60.0f
#define BETA  20.0f
#define EPSC  1e-8f

// ---- scratch (allocation-free: __device__ globals) ----
__device__ float g_p1[3][2][BSZ * HDIM];    // P1 partials (pre-tanh, pre-bias)
__device__ float g_p2[3][8][BSZ * NDIM];    // P2 partials (pre-bias)
__device__ float g_p3[2][4][BSZ * HDIM];    // P3 partials (pre *D)
__device__ float g_p4[2][16][BSZ * NDIM];   // P4 partials (Jf, JG)
__device__ float g_D  [BSZ * HDIM];         // 1 - tanh^2 for k
__device__ float g_fgk[3][BSZ * NDIM];      // materialized f, g, k

// ---- barrier / work-stealing state ----
__device__ int g_cnt   = 0;
__device__ int g_sense = 0;
__device__ int g_ctr[4] = {0, 0, 0, 0};     // tile tickets: P1..P4

// Sense-reversing grid barrier (capture/replay safe, no epoch capture).
// Last arriver optionally resets a ticket counter before releasing.
__device__ __forceinline__ void gbar(int* rst)
{
    __threadfence();
    __syncthreads();
    if (threadIdx.x == 0) {
        int s = *(volatile int*)&g_sense;
        int old = atomicAdd(&g_cnt, 1);
        if (old == (int)gridDim.x - 1) {
            atomicExch(&g_cnt, 0);
            if (rst) atomicExch(rst, 0);
            __threadfence();
            atomicExch(&g_sense, 1 - s);
        } else {
            while (*(volatile int*)&g_sense == s) __nanosleep(64);
        }
        __threadfence();
    }
    __syncthreads();
}

// ---- packed fp32x2 helpers ----
__device__ __forceinline__ ull pk2(float x, float y)
{
    ull r;
    asm("mov.b64 %0, {%1, %2};" : "=l"(r)
        : "r"(__float_as_uint(x)), "r"(__float_as_uint(y)));
    return r;
}
__device__ __forceinline__ void upk2(ull v, float& x, float& y)
{
    unsigned a, b;
    asm("mov.b64 {%0, %1}, %2;" : "=r"(a), "=r"(b) : "l"(v));
    x = __uint_as_float(a);
    y = __uint_as_float(b);
}
#define FMA2(d, a, b) asm("fma.rn.f32x2 %0, %1, %2, %0;" : "+l"(d) : "l"(a), "l"(b))

__device__ __forceinline__ float4 ld4(const float* p)
{
    return *reinterpret_cast<const float4*>(p);
}

// ---- A-tile loaders (k is GLOBAL k index, float4-aligned) ----
struct DirectA {
    const float* p; int ld;
    __device__ __forceinline__ float4 operator()(int row, int k) const {
        return ld4(&p[(size_t)row * ld + k]);
    }
};
struct TanhA {                 // H = tanh(p1_0 + p1_1 + b1); optionally write D
    const float* p0; const float* p1; const float* b; float* D;
    __device__ __forceinline__ float4 operator()(int row, int k) const {
        const size_t o = (size_t)row * HDIM + k;
        float4 u = ld4(p0 + o), v = ld4(p1 + o), bb = ld4(b + k);
        float4 t;
        t.x = tanhf(u.x + v.x + bb.x);
        t.y = tanhf(u.y + v.y + bb.y);
        t.z = tanhf(u.z + v.z + bb.z);
        t.w = tanhf(u.w + v.w + bb.w);
        if (D) {
            float4 d;
            d.x = 1.0f - t.x * t.x; d.y = 1.0f - t.y * t.y;
            d.z = 1.0f - t.z * t.z; d.w = 1.0f - t.w * t.w;
            *reinterpret_cast<float4*>(D + o) = d;
        }
        return t;
    }
};
struct DvA {                   // dv = (p3_0+p3_1+p3_2+p3_3) * D
    const float* q0; const float* q1; const float* q2; const float* q3;
    const float* Dp;
    __device__ __forceinline__ float4 operator()(int row, int k) const {
        const size_t o = (size_t)row * HDIM + k;
        float4 a = ld4(q0 + o), b = ld4(q1 + o), c = ld4(q2 + o), d = ld4(q3 + o);
        float4 dd = ld4(Dp + o);
        float4 v;
        v.x = (a.x + b.x + c.x + d.x) * dd.x;
        v.y = (a.y + b.y + c.y + d.y) * dd.y;
        v.z = (a.z + b.z + c.z + d.z) * dd.z;
        v.w = (a.w + b.w + c.w + d.w) * dd.w;
        return v;
    }
};

// ============================================================
// 64x64 tile GEMM, BK=32, 256 threads, 4x4 per thread via fp32x2.
// BT=true : C[m,n] = sum_k A[m,k] * B[n*ldb+k]   (NT)
// BT=false: C[m,n] = sum_k A[m,k] * B[k*ldb+n]   (NN)
// B pre-offset to the K-chunk; A loader receives global k via kbase.
// acc[p][j]: packed pair (rows tm+2p, tm+2p+1) at column tn+j.
// ============================================================
template <bool BT, class AL>
__device__ __forceinline__ void gemm32(
    const AL& la, int kbase,
    const float* __restrict__ B, int ldb,
    int K, int bm, int bn, ull acc[2][4],
    float (&As)[32][68], float (&Bs)[32][68])
{
    const int tid = threadIdx.x;
    const int tm = (tid >> 4) * 4;
    const int tn = (tid & 15) * 4;
    const int lr = tid >> 2;          // 0..63
    const int lc = (tid & 3) * 4;     // 0,4,8,12
    const int br = tid >> 3;          // 0..31
    const int bc = (tid & 7) * 8;     // 0..56

    for (int k0 = 0; k0 < K; k0 += 32) {
        float4 a0 = la(bm + lr, kbase + k0 + lc);
        float4 a1 = la(bm + lr, kbase + k0 + lc + 16);
        As[lc + 0][lr] = a0.x;  As[lc + 1][lr] = a0.y;
        As[lc + 2][lr] = a0.z;  As[lc + 3][lr] = a0.w;
        As[lc + 16][lr] = a1.x; As[lc + 17][lr] = a1.y;
        As[lc + 18][lr] = a1.z; As[lc + 19][lr] = a1.w;
        if (BT) {
            float4 b0 = ld4(&B[(size_t)(bn + lr) * ldb + k0 + lc]);
            float4 b1 = ld4(&B[(size_t)(bn + lr) * ldb + k0 + lc + 16]);
            Bs[lc + 0][lr] = b0.x;  Bs[lc + 1][lr] = b0.y;
            Bs[lc + 2][lr] = b0.z;  Bs[lc + 3][lr] = b0.w;
            Bs[lc + 16][lr] = b1.x; Bs[lc + 17][lr] = b1.y;
            Bs[lc + 18][lr] = b1.z; Bs[lc + 19][lr] = b1.w;
        } else {
            float4 b0 = ld4(&B[(size_t)(k0 + br) * ldb + bn + bc]);
            float4 b1 = ld4(&B[(size_t)(k0 + br) * ldb + bn + bc + 4]);
            *reinterpret_cast<float4*>(&Bs[br][bc])     = b0;
            *reinterpret_cast<float4*>(&Bs[br][bc + 4]) = b1;
        }
        __syncthreads();
#pragma unroll
        for (int kk = 0; kk < 32; kk++) {
            float4 a4 = ld4(&As[kk][tm]);
            float4 b4 = ld4(&Bs[kk][tn]);
            ull ap0 = pk2(a4.x, a4.y);
            ull ap1 = pk2(a4.z, a4.w);
            ull bd0 = pk2(b4.x, b4.x);
            ull bd1 = pk2(b4.y, b4.y);
            ull bd2 = pk2(b4.z, b4.z);
            ull bd3 = pk2(b4.w, b4.w);
            FMA2(acc[0][0], ap0, bd0); FMA2(acc[1][0], ap1, bd0);
            FMA2(acc[0][1], ap0, bd1); FMA2(acc[1][1], ap1, bd1);
            FMA2(acc[0][2], ap0, bd2); FMA2(acc[1][2], ap1, bd2);
            FMA2(acc[0][3], ap0, bd3); FMA2(acc[1][3], ap1, bd3);
        }
        __syncthreads();
    }
}

__device__ __forceinline__ void store_acc(float* __restrict__ out, int ld,
                                          int bm, int bn, ull acc[2][4])
{
    const int tid = threadIdx.x;
    const int tm = (tid >> 4) * 4, tn = (tid & 15) * 4;
    float c[4][4];
#pragma unroll
    for (int p = 0; p < 2; p++)
#pragma unroll
        for (int j = 0; j < 4; j++)
            upk2(acc[p][j], c[2 * p][j], c[2 * p + 1][j]);
#pragma unroll
    for (int i = 0; i < 4; i++) {
        float4 v = make_float4(c[i][0], c[i][1], c[i][2], c[i][3]);
        *reinterpret_cast<float4*>(&out[(size_t)(bm + tm + i) * ld + bn + tn]) = v;
    }
}

#define ZERO_ACC(acc) do {                       \
    _Pragma("unroll") for (int p = 0; p < 2; p++) \
    _Pragma("unroll") for (int j = 0; j < 4; j++) \
        acc[p][j] = 0ull; } while (0)

// ============================================================
// Persistent kernel: 5 phases + materialize, work-stealing tiles.
// ============================================================
__global__ __launch_bounds__(256, 2) void fused_kernel(
    const float* __restrict__ x,
    const float* __restrict__ Wf1, const float* __restrict__ bf1,
    const float* __restrict__ Wf2, const float* __restrict__ bf2,
    const float* __restrict__ Wg1, const float* __restrict__ bg1,
    const float* __restrict__ Wg2, const float* __restrict__ bg2,
    const float* __restrict__ Wk1, const float* __restrict__ bk1,
    const float* __restrict__ Wk2, const float* __restrict__ bk2,
    float* __restrict__ out)
{
    __shared__ float As[32][68];
    __shared__ float Bs[32][68];
    __shared__ int s_t;

    const int tid = threadIdx.x;
    const int bid = blockIdx.x;

    // ---------- Phase 1: p1[z][s] = x[:,chunk] @ W1[z][:,chunk]^T ----------
    // 192 tiles: z3 x s2(K=128) x m2 x n16
    for (;;) {
        __syncthreads();
        if (tid == 0) s_t = atomicAdd(&g_ctr[0], 1);
        __syncthreads();
        const int t = s_t;
        if (t >= 192) break;
        const int z = t >> 6, r = t & 63;
        const int s = r >> 5, rr = r & 31;
        const int bm = (rr >> 4) * 64, bn = (rr & 15) * 64;
        const float* W = (z == 0) ? Wf1 : (z == 1) ? Wg1 : Wk1;
        ull acc[2][4]; ZERO_ACC(acc);
        DirectA la{x, NDIM};
        gemm32<true>(la, s * 128, W + s * 128, NDIM, 128, bm, bn, acc, As, Bs);
        store_acc(g_p1[z][s], HDIM, bm, bn, acc);
    }
    gbar(&g_ctr[1]);

    // ---------- Phase 2: p2[z][s] = tanh(p1sum+b1)[:,chunk] @ W2[z][:,chunk]^T ----
    // 192 tiles: z3 x s8(K=128) x m2 x n4.  (z==2,n==0) blocks also emit D.
    for (;;) {
        __syncthreads();
        if (tid == 0) s_t = atomicAdd(&g_ctr[1], 1);
        __syncthreads();
        const int t = s_t;
        if (t >= 192) break;
        const int z = t >> 6, r = t & 63;
        const int s = r >> 3, rr = r & 7;
        const int bm = (rr >> 2) * 64, bn = (rr & 3) * 64;
        const float* W  = (z == 0) ? Wf2 : (z == 1) ? Wg2 : Wk2;
        const float* b1 = (z == 0) ? bf1 : (z == 1) ? bg1 : bk1;
        ull acc[2][4]; ZERO_ACC(acc);
        TanhA la{g_p1[z][0], g_p1[z][1], b1,
                 (z == 2 && (rr & 3) == 0) ? g_D : (float*)nullptr};
        gemm32<true>(la, s * 128, W + s * 128, HDIM, 128, bm, bn, acc, As, Bs);
        store_acc(g_p2[z][s], NDIM, bm, bn, acc);
    }
    gbar(&g_ctr[2]);

    // ---------- Phase 2b: materialize f, g, k = sum_s p2 + b2 ----------
    {
        const int total4 = 3 * BSZ * NDIM / 4;
        for (int i = bid * 256 + tid; i < total4; i += gridDim.x * 256) {
            const int z = i / (BSZ * NDIM / 4);
            const int j = i - z * (BSZ * NDIM / 4);
            const int col4 = j & (NDIM / 4 - 1);
            const float* b2 = (z == 0) ? bf2 : (z == 1) ? bg2 : bk2;
            float4 acc = reinterpret_cast<const float4*>(b2)[col4];
#pragma unroll
            for (int s = 0; s < 8; s++) {
                float4 p = reinterpret_cast<const float4*>(g_p2[z][s])[j];
                acc.x += p.x; acc.y += p.y; acc.z += p.z; acc.w += p.w;
            }
            reinterpret_cast<float4*>(g_fgk[z])[j] = acc;
        }
    }
    gbar(&g_ctr[3]);

    // ---------- Phase 3: p3[z][s] = {f,g}[:,chunk] @ Wk2[chunk,:]  (NN) ----------
    // 256 tiles: z2 x s4(K=64) x m2 x n16
    for (;;) {
        __syncthreads();
        if (tid == 0) s_t = atomicAdd(&g_ctr[2], 1);
        __syncthreads();
        const int t = s_t;
        if (t >= 256) break;
        const int z = t >> 7, r = t & 127;
        const int s = r >> 5, rr = r & 31;
        const int bm = (rr >> 4) * 64, bn = (rr & 15) * 64;
        ull acc[2][4]; ZERO_ACC(acc);
        DirectA la{g_fgk[z], NDIM};
        gemm32<false>(la, s * 64, Wk2 + (size_t)(s * 64) * HDIM, HDIM,
                      64, bm, bn, acc, As, Bs);
        store_acc(g_p3[z][s], HDIM, bm, bn, acc);
    }
    gbar(&g_ctr[0]);   // reset P1 ticket for next launch

    // ---------- Phase 4: p4[z][s] = dv[z][:,chunk] @ Wk1[chunk,:]  (NN) ----------
    // 256 tiles: z2 x s16(K=64) x m2 x n4;  dv reconstructed in loader
    for (;;) {
        __syncthreads();
        if (tid == 0) s_t = atomicAdd(&g_ctr[3], 1);
        __syncthreads();
        const int t = s_t;
        if (t >= 256) break;
        const int z = t >> 7, r = t & 127;
        const int s = r >> 3, rr = r & 7;
        const int bm = (rr >> 2) * 64, bn = (rr & 3) * 64;
        ull acc[2][4]; ZERO_ACC(acc);
        DvA la{g_p3[z][0], g_p3[z][1], g_p3[z][2], g_p3[z][3], g_D};
        gemm32<false>(la, s * 64, Wk1 + (size_t)(s * 64) * NDIM, NDIM,
                      64, bm, bn, acc, As, Bs);
        store_acc(g_p4[z][s], NDIM, bm, bn, acc);
    }
    gbar(nullptr);

    // ---------- Phase 5: reduce + norms + mask + output (blocks 0..127) ----------
    if (bid < BSZ) {
        const int b = bid, i = tid;
        const int idx = b * NDIM + i;

        float jfv = 0.f, jgv = 0.f;
#pragma unroll
        for (int s = 0; s < 16; s++) {
            jfv += g_p4[0][s][idx];
            jgv += g_p4[1][s][idx];
        }
        const float fv = g_fgk[0][idx];
        const float gv = g_fgk[1][idx];
        const float kv = g_fgk[2][idx];

        float kn2 = kv * kv;
        float jf2 = jfv * jfv;
        float dt  = kv * jgv;
#pragma unroll
        for (int off = 16; off > 0; off >>= 1) {
            kn2 += __shfl_down_sync(0xffffffffu, kn2, off);
            jf2 += __shfl_down_sync(0xffffffffu, jf2, off);
            dt  += __shfl_down_sync(0xffffffffu, dt,  off);
        }

        __shared__ float s_kn2[8], s_jf2[8], s_dt[8];
        __shared__ float s_scale;
        const int warp = i >> 5, lane = i & 31;
        if (lane == 0) { s_kn2[warp] = kn2; s_jf2[warp] = jf2; s_dt[warp] = dt; }
        __syncthreads();
        if (i == 0) {
            float tkn2 = 0.f, tjf2 = 0.f, tdt = 0.f;
#pragma unroll
            for (int w = 0; w < 8; w++) { tkn2 += s_kn2[w]; tjf2 += s_jf2[w]; tdt += s_dt[w]; }
            const float kn   = sqrtf(tkn2);
            const float kn9  = tkn2 * tkn2 * tkn2 * tkn2 * kn;
            const float kn10 = kn9 * kn;
            const float c1 = sqrtf(tjf2) - ALPHA * kn9;
            const float c2 = tdt - BETA * kn10;
            const bool mask = (c1 > EPSC) || (c2 < -EPSC);
            s_scale = mask ? 0.5f : 1.0f;
        }
        __syncthreads();
        out[idx] = s_scale * (fv + gv);
    }
}

// inputs: 0:t 1:x 2:Wf1 3:bf1 4:Wf2 5:bf2 6:Wg1 7:bg1 8:Wg2 9:bg2 10:Wk1 11:bk1 12:Wk2 13:bk2
extern "C" void kernel_launch(void* const* d_in, const int* in_sizes, int n_in,
                              void* d_out, int out_size)
{
    const float* x   = (const float*)d_in[1];
    const float* Wf1 = (const float*)d_in[2];
    const float* bf1 = (const float*)d_in[3];
    const float* Wf2 = (const float*)d_in[4];
    const float* bf2 = (const float*)d_in[5];
    const float* Wg1 = (const float*)d_in[6];
    const float* bg1 = (const float*)d_in[7];
    const float* Wg2 = (const float*)d_in[8];
    const float* bg2 = (const float*)d_in[9];
    const float* Wk1 = (const float*)d_in[10];
    const float* bk1 = (const float*)d_in[11];
    const float* Wk2 = (const float*)d_in[12];
    const float* bk2 = (const float*)d_in[13];
    float* out = (float*)d_out;

    int dev = 0;
    cudaGetDevice(&dev);
    int sms = 148;
    cudaDeviceGetAttribute(&sms, cudaDevAttrMultiProcessorCount, dev);
    int occ = 1;
    cudaOccupancyMaxActiveBlocksPerMultiprocessor(&occ, fused_kernel, 256, 0);
    if (occ < 1) occ = 1;
    if (occ > 2) occ = 2;
    int grid = sms * occ;          // all blocks co-resident -> barrier-safe

    fused_kernel<<<grid, 256>>>(x, Wf1, bf1, Wf2, bf2, Wg1, bg1, Wg2, bg2,
                                Wk1, bk1, Wk2, bk2, out);
}